// round 17
// baseline (speedup 1.0000x reference)
#include <cuda_runtime.h>
#include <cuda_fp16.h>
#include <cstdint>

#define K_DIM   784
#define H_DIM   1024
#define O_DIM   10
#define B_SIZE  128
#define T_STEPS 200
#define M_TOTAL (B_SIZE * T_STEPS)
#define BETA    0.95f
#define LO_SCALE 2048.0f
#define LO_INV  (1.0f / 2048.0f)

#define E_TOT   4.1e-5f
#define MAXF    1024

// GEMM tiling: BK=16, no K padding, 5-stage pipeline, 2 CTA/SM
#define BM 128
#define BN 64
#define BK 16
#define NCH (K_DIM / BK)           // 49
#define ROWB 48
#define A_MAT_BYTES (BM * ROWB)    // 6144
#define B_MAT_BYTES (BN * ROWB)    // 3072
#define OFF_AHI 0
#define OFF_ALO (A_MAT_BYTES)
#define OFF_BHI (2 * A_MAT_BYTES)
#define OFF_BLO (2 * A_MAT_BYTES + B_MAT_BYTES)
#define STAGE_BYTES (2 * A_MAT_BYTES + 2 * B_MAT_BYTES)   // 18432
#define NSTAGE 5
#define SMEM_TOTAL (NSTAGE * STAGE_BYTES)                 // 92160

#define XS_WORDS (784 * 33)
#define FILL_SMEM (XS_WORDS * 4)

__device__ float    g_cur1[(size_t)M_TOTAL * H_DIM];
__device__ __half   g_Ahi[(size_t)M_TOTAL * K_DIM];
__device__ __half   g_Aslo[(size_t)M_TOTAL * K_DIM];
__device__ __half   g_Bhi[(size_t)H_DIM * K_DIM];
__device__ __half   g_Bslo[(size_t)H_DIM * K_DIM];
__device__ unsigned g_spk[(size_t)M_TOTAL * (H_DIM / 32)];
__device__ int      g_flagcnt[B_SIZE];
__device__ unsigned short g_flaglist[B_SIZE * MAXF];

// ---------------- helpers ----------------
__device__ __forceinline__ uint32_t smem_u32(const void* p) {
    uint32_t a;
    asm("{ .reg .u64 t; cvta.to.shared.u64 t, %1; cvt.u32.u64 %0, t; }" : "=r"(a) : "l"(p));
    return a;
}
__device__ __forceinline__ void cp_async16(uint32_t dst, const void* src) {
    asm volatile("cp.async.cg.shared.global [%0], [%1], 16;" :: "r"(dst), "l"(src) : "memory");
}
__device__ __forceinline__ void ldsm_x4(uint32_t (&r)[4], uint32_t addr) {
    asm volatile("ldmatrix.sync.aligned.m8n8.x4.shared.b16 {%0,%1,%2,%3}, [%4];"
                 : "=r"(r[0]), "=r"(r[1]), "=r"(r[2]), "=r"(r[3]) : "r"(addr));
}
__device__ __forceinline__ void mma16816(float (&d)[4], const uint32_t (&a)[4],
                                         const uint32_t b0, const uint32_t b1) {
    asm volatile("mma.sync.aligned.m16n8k16.row.col.f32.f16.f16.f32 "
                 "{%0,%1,%2,%3}, {%4,%5,%6,%7}, {%8,%9}, {%0,%1,%2,%3};"
                 : "+f"(d[0]), "+f"(d[1]), "+f"(d[2]), "+f"(d[3])
                 : "r"(a[0]), "r"(a[1]), "r"(a[2]), "r"(a[3]), "r"(b0), "r"(b1));
}

// ---------------------------------------------------------------------------
// Combined split: rows [0, M_TOTAL) = x, rows [M_TOTAL, M_TOTAL+H_DIM) = w1.
// ---------------------------------------------------------------------------
__global__ void split_all(const float* __restrict__ x, const float* __restrict__ w1) {
    const size_t row = blockIdx.y;
    const int col = blockIdx.x * 256 + threadIdx.x;
    if (row == 0 && blockIdx.x == 0 && threadIdx.x < B_SIZE)
        g_flagcnt[threadIdx.x] = 0;
    if (col >= K_DIM) return;

    float v;
    __half* hi;
    __half* lo;
    size_t oi;
    if (row < (size_t)M_TOTAL) {
        v = x[row * K_DIM + col];
        oi = row * K_DIM + col;
        hi = g_Ahi; lo = g_Aslo;
    } else {
        const size_t r = row - M_TOTAL;
        v = w1[r * K_DIM + col];
        oi = r * K_DIM + col;
        hi = g_Bhi; lo = g_Bslo;
    }
    const __half h = __float2half_rn(v);
    const float res = v - __half2float(h);
    hi[oi] = h;
    lo[oi] = __float2half_rn(res * LO_SCALE);
}

// ---------------------------------------------------------------------------
// Approx GEMM1: cur1 = A@W^T + b1, fp16 hi/lo split mma.sync.
// BK=16, 49 chunks, 12 MMAs/chunk, 5-stage cp.async, 2 CTA/SM.
// ---------------------------------------------------------------------------
__global__ __launch_bounds__(256, 2) void gemm1_mma(const float* __restrict__ bias) {
    extern __shared__ char smem[];
    const uint32_t sb = smem_u32(smem);
    const int tid  = threadIdx.x;
    const int lane = tid & 31;
    const int wid  = tid >> 5;
    const int wm   = wid & 3;
    const int wn   = wid >> 2;
    const int bm   = blockIdx.y * BM;
    const int bn   = blockIdx.x * BN;

    auto load_stage = [&](int c) {
        const uint32_t base = sb + (uint32_t)(c % NSTAGE) * STAGE_BYTES;
        const int kc = c * BK;
        {
            const int r = tid >> 1, ch = tid & 1;
            const uint32_t doff = (uint32_t)r * ROWB + ch * 16;
            const size_t gsrc = (size_t)(bm + r) * K_DIM + kc + ch * 8;
            cp_async16(base + OFF_AHI + doff, g_Ahi  + gsrc);
            cp_async16(base + OFF_ALO + doff, g_Aslo + gsrc);
        }
        if (tid < 128) {
            const int r = tid >> 1, ch = tid & 1;
            const uint32_t doff = (uint32_t)r * ROWB + ch * 16;
            const size_t gsrc = (size_t)(bn + r) * K_DIM + kc + ch * 8;
            cp_async16(base + OFF_BHI + doff, g_Bhi  + gsrc);
            cp_async16(base + OFF_BLO + doff, g_Bslo + gsrc);
        }
        asm volatile("cp.async.commit_group;" ::: "memory");
    };

    load_stage(0); load_stage(1); load_stage(2); load_stage(3);

    const uint32_t aoff0 = (uint32_t)(wm * 32 +  0 + (lane & 15)) * ROWB + ((lane >> 4) << 4);
    const uint32_t aoff1 = (uint32_t)(wm * 32 + 16 + (lane & 15)) * ROWB + ((lane >> 4) << 4);
    const uint32_t boff0 = (uint32_t)(wn * 32 +  0 + (lane & 7) + ((lane >> 4) << 3)) * ROWB
                         + ((lane & 8) ? 16u : 0u);
    const uint32_t boff1 = (uint32_t)(wn * 32 + 16 + (lane & 7) + ((lane >> 4) << 3)) * ROWB
                         + ((lane & 8) ? 16u : 0u);

    float accm[2][4][4], accc[2][4][4];
    #pragma unroll
    for (int i = 0; i < 2; i++)
        #pragma unroll
        for (int j = 0; j < 4; j++)
            #pragma unroll
            for (int k = 0; k < 4; k++) { accm[i][j][k] = 0.f; accc[i][j][k] = 0.f; }

    for (int c = 0; c < NCH; c++) {
        asm volatile("cp.async.wait_group 3;" ::: "memory");
        __syncthreads();
        if (c + 4 < NCH) load_stage(c + 4);

        const uint32_t base = sb + (uint32_t)(c % NSTAGE) * STAGE_BYTES;
        uint32_t ah0[4], ah1[4], al0[4], al1[4];
        uint32_t bh0[4], bh1[4], bl0[4], bl1[4];
        ldsm_x4(ah0, base + OFF_AHI + aoff0);
        ldsm_x4(ah1, base + OFF_AHI + aoff1);
        ldsm_x4(al0, base + OFF_ALO + aoff0);
        ldsm_x4(al1, base + OFF_ALO + aoff1);
        ldsm_x4(bh0, base + OFF_BHI + boff0);
        ldsm_x4(bh1, base + OFF_BHI + boff1);
        ldsm_x4(bl0, base + OFF_BLO + boff0);
        ldsm_x4(bl1, base + OFF_BLO + boff1);

        #pragma unroll
        for (int nt = 0; nt < 4; nt++) {
            const uint32_t* bh = (nt < 2) ? bh0 : bh1;
            const int o = (nt & 1) * 2;
            mma16816(accm[0][nt], ah0, bh[o], bh[o + 1]);
            mma16816(accm[1][nt], ah1, bh[o], bh[o + 1]);
        }
        #pragma unroll
        for (int nt = 0; nt < 4; nt++) {
            const uint32_t* bl = (nt < 2) ? bl0 : bl1;
            const int o = (nt & 1) * 2;
            mma16816(accc[0][nt], ah0, bl[o], bl[o + 1]);
            mma16816(accc[1][nt], ah1, bl[o], bl[o + 1]);
        }
        #pragma unroll
        for (int nt = 0; nt < 4; nt++) {
            const uint32_t* bh = (nt < 2) ? bh0 : bh1;
            const int o = (nt & 1) * 2;
            mma16816(accc[0][nt], al0, bh[o], bh[o + 1]);
            mma16816(accc[1][nt], al1, bh[o], bh[o + 1]);
        }
    }

    #pragma unroll
    for (int mt = 0; mt < 2; mt++) {
        const int r0 = bm + wm * 32 + mt * 16 + (lane >> 2);
        #pragma unroll
        for (int nt = 0; nt < 4; nt++) {
            const int col = bn + wn * 32 + nt * 8 + (lane & 3) * 2;
            const float b0 = bias[col], b1 = bias[col + 1];
            float2 v0, v1;
            v0.x = accm[mt][nt][0] + accc[mt][nt][0] * LO_INV + b0;
            v0.y = accm[mt][nt][1] + accc[mt][nt][1] * LO_INV + b1;
            v1.x = accm[mt][nt][2] + accc[mt][nt][2] * LO_INV + b0;
            v1.y = accm[mt][nt][3] + accc[mt][nt][3] * LO_INV + b1;
            *(float2*)&g_cur1[(size_t)r0 * H_DIM + col]       = v0;
            *(float2*)&g_cur1[(size_t)(r0 + 8) * H_DIM + col] = v1;
        }
    }
}

// ---------------------------------------------------------------------------
// Phase A + certification flagging; MLP-16 load batching.
// ---------------------------------------------------------------------------
__global__ __launch_bounds__(256) void phaseA_flag() {
    const int gid = blockIdx.x * 256 + threadIdx.x;
    const int b = gid >> 10;
    const int h = gid & 1023;
    const int lane = threadIdx.x & 31;

    const float* cp = g_cur1 + (size_t)b * T_STEPS * H_DIM + h;
    unsigned* sp = g_spk + (size_t)b * T_STEPS * 32 + (h >> 5);

    float mem = 0.f, spk = 0.f, e = 0.f;
    bool flag = false;

    float cb[16];
    #pragma unroll
    for (int i = 0; i < 16; i++) cb[i] = cp[(size_t)i * H_DIM];

    for (int t0 = 0; t0 < T_STEPS; t0 += 16) {
        float cn[16];
        #pragma unroll
        for (int i = 0; i < 16; i++) cn[i] = 0.f;
        if (t0 + 16 < T_STEPS) {
            #pragma unroll
            for (int i = 0; i < 16; i++)
                cn[i] = cp[(size_t)(t0 + 16 + i) * H_DIM];
        }
        #pragma unroll
        for (int i = 0; i < 16; i++) {
            if (t0 + i >= T_STEPS) break;
            mem = fmaf(BETA, mem, cb[i]) - spk;
            e   = fmaf(BETA, e, E_TOT);
            flag |= (fabsf(mem - 1.0f) <= e);
            const bool up = mem > 1.0f;
            spk = up ? 1.0f : 0.0f;
            const unsigned bal = __ballot_sync(0xffffffffu, up);
            if (lane == 0) sp[(size_t)(t0 + i) * 32] = bal;
        }
        #pragma unroll
        for (int i = 0; i < 16; i++) cb[i] = cn[i];
    }
    if (flag) {
        int idx = atomicAdd(&g_flagcnt[b], 1);
        g_flaglist[b * MAXF + idx] = (unsigned short)h;
    }
}

// ---------------------------------------------------------------------------
// repair_fill: CTA per (b, t0-block); exact strict-k fp32 chains for flagged h.
// ---------------------------------------------------------------------------
__global__ __launch_bounds__(256) void repair_fill(
    const float* __restrict__ x, const float* __restrict__ w1,
    const float* __restrict__ b1)
{
    extern __shared__ float Xs[];
    const int b  = blockIdx.x;
    const int Hf = g_flagcnt[b];
    if (Hf == 0) return;
    const int t0   = blockIdx.y * 32;
    const int tid  = threadIdx.x;
    const int warp = tid >> 5;
    const int lane = tid & 31;

    for (int i = tid; i < 32 * 196; i += 256) {
        const int trow = i / 196, kq = i % 196;
        float4 v = make_float4(0.f, 0.f, 0.f, 0.f);
        if (t0 + trow < T_STEPS)
            v = *(const float4*)&x[((size_t)b * T_STEPS + t0 + trow) * K_DIM + kq * 4];
        Xs[(kq * 4 + 0) * 33 + trow] = v.x;
        Xs[(kq * 4 + 1) * 33 + trow] = v.y;
        Xs[(kq * 4 + 2) * 33 + trow] = v.z;
        Xs[(kq * 4 + 3) * 33 + trow] = v.w;
    }
    __syncthreads();

    const int t = t0 + lane;
    for (int fi = warp; fi < Hf; fi += 8) {
        const int h = g_flaglist[b * MAXF + fi];
        const float* wr = w1 + (size_t)h * K_DIM;
        float acc = 0.f;
        #pragma unroll 4
        for (int k0 = 0; k0 < K_DIM; k0 += 8) {
            const float4 w0 = *(const float4*)(wr + k0);
            const float4 w4 = *(const float4*)(wr + k0 + 4);
            acc = fmaf(Xs[(k0 + 0) * 33 + lane], w0.x, acc);
            acc = fmaf(Xs[(k0 + 1) * 33 + lane], w0.y, acc);
            acc = fmaf(Xs[(k0 + 2) * 33 + lane], w0.z, acc);
            acc = fmaf(Xs[(k0 + 3) * 33 + lane], w0.w, acc);
            acc = fmaf(Xs[(k0 + 4) * 33 + lane], w4.x, acc);
            acc = fmaf(Xs[(k0 + 5) * 33 + lane], w4.y, acc);
            acc = fmaf(Xs[(k0 + 6) * 33 + lane], w4.z, acc);
            acc = fmaf(Xs[(k0 + 7) * 33 + lane], w4.w, acc);
        }
        if (t < T_STEPS)
            g_cur1[((size_t)b * T_STEPS + t) * H_DIM + h] = acc + b1[h];
    }
}

// ---------------------------------------------------------------------------
// rescan: one thread per flagged pair; exact scan, patch bits.
// ---------------------------------------------------------------------------
__global__ __launch_bounds__(256) void repair_rescan() {
    const int id = blockIdx.x * 256 + threadIdx.x;
    const int b  = id >> 10;
    const int fi = id & (MAXF - 1);
    if (b >= B_SIZE || fi >= g_flagcnt[b]) return;

    const int h = g_flaglist[b * MAXF + fi];
    const float* cp = g_cur1 + (size_t)b * T_STEPS * H_DIM + h;
    const unsigned mask = 1u << (h & 31);
    float mem = 0.f, spk = 0.f;
    for (int t = 0; t < T_STEPS; t++) {
        mem = fmaf(BETA, mem, cp[(size_t)t * H_DIM]) - spk;
        const bool up = mem > 1.0f;
        spk = up ? 1.0f : 0.0f;
        unsigned* wp = &g_spk[((size_t)b * T_STEPS + t) * 32 + (h >> 5)];
        if (up) atomicOr(wp, mask);
        else    atomicAnd(wp, ~mask);
    }
}

// ---------------------------------------------------------------------------
// Fused Phase B+C (validated in R16, unchanged).
// ---------------------------------------------------------------------------
__global__ __launch_bounds__(256) void phaseBC_kernel(
    const float* __restrict__ w2, const float* __restrict__ b2,
    float* __restrict__ out_spk, float* __restrict__ out_mem)
{
    __shared__ float w2s[H_DIM * O_DIM];
    __shared__ float c2s[T_STEPS * O_DIM];
    const int b = blockIdx.x;
    const int tid = threadIdx.x;

    for (int i = tid; i < H_DIM * O_DIM; i += 256) {
        const int o = i / H_DIM, h = i % H_DIM;
        w2s[h * O_DIM + o] = w2[i];
    }
    __syncthreads();

    if (tid < T_STEPS) {
        const int row = b * T_STEPS + tid;
        float acc[O_DIM];
        #pragma unroll
        for (int o = 0; o < O_DIM; o++) acc[o] = 0.f;

        const unsigned* sw = g_spk + (size_t)row * 32;
        for (int wb = 0; wb < 32; wb++) {
            const unsigned bits = sw[wb];
            #pragma unroll 8
            for (int j = 0; j < 32; j++) {
                const float f = ((bits >> j) & 1u) ? 1.0f : 0.0f;
                const float* wp = &w2s[(wb * 32 + j) * O_DIM];
                #pragma unroll
                for (int o = 0; o < O_DIM; o++)
                    acc[o] = fmaf(f, wp[o], acc[o]);
            }
        }
        #pragma unroll
        for (int o = 0; o < O_DIM; o++) c2s[tid * O_DIM + o] = acc[o];
    }
    __syncthreads();

    if (tid < O_DIM) {
        const int o = tid;
        const float bias = b2[o];
        float* os = out_spk + (size_t)b * T_STEPS * O_DIM + o;
        float* om = out_mem + (size_t)b * T_STEPS * O_DIM + o;
        float mem = 0.f, spk = 0.f;
        for (int t = 0; t < T_STEPS; t++) {
            const float c = c2s[t * O_DIM + o];
            mem = fmaf(BETA, mem, c + bias) - spk;
            spk = (mem > 1.0f) ? 1.0f : 0.0f;
            os[(size_t)t * O_DIM] = spk;
            om[(size_t)t * O_DIM] = mem;
        }
    }
}

// ---------------------------------------------------------------------------
extern "C" void kernel_launch(void* const* d_in, const int* in_sizes, int n_in,
                              void* d_out, int out_size)
{
    const float* x  = (const float*)d_in[0];
    const float* w1 = (const float*)d_in[1];
    const float* b1 = (const float*)d_in[2];
    const float* w2 = (const float*)d_in[3];
    const float* b2 = (const float*)d_in[4];
    float* out = (float*)d_out;

    cudaFuncSetAttribute(gemm1_mma, cudaFuncAttributeMaxDynamicSharedMemorySize, SMEM_TOTAL);
    cudaFuncSetAttribute(repair_fill, cudaFuncAttributeMaxDynamicSharedMemorySize, FILL_SMEM);

    dim3 gsp((K_DIM + 255) / 256, M_TOTAL + H_DIM);
    split_all<<<gsp, 256>>>(x, w1);

    dim3 gg(H_DIM / BN, M_TOTAL / BM);             // (16, 200)
    gemm1_mma<<<gg, 256, SMEM_TOTAL>>>(b1);

    phaseA_flag<<<(B_SIZE * H_DIM) / 256, 256>>>();
    repair_fill<<<dim3(B_SIZE, (T_STEPS + 31) / 32), 256, FILL_SMEM>>>(x, w1, b1);
    repair_rescan<<<(B_SIZE * MAXF) / 256, 256>>>();

    phaseBC_kernel<<<B_SIZE, 256>>>(w2, b2, out, out + (size_t)B_SIZE * T_STEPS * O_DIM);
}